// round 4
// baseline (speedup 1.0000x reference)
#include <cuda_runtime.h>
#include <cuda_bf16.h>
#include <cstdint>

#define D 1024
#define NB 8
#define NT 64
#define NS 32
#define NE 16
#define NV 50257
#define M_TOT 768          // 512 q rows + 256 k rows

// tcgen05 only exists in the arch-SPECIFIC (sm_103a) device pass.
#if defined(__CUDA_ARCH_FEAT_SM103_ALL) || \
    (defined(__CUDA_ARCH_SPECIFIC__) && (__CUDA_ARCH_SPECIFIC__ == 1030))
#define HAS_TCGEN05 1
#else
#define HAS_TCGEN05 0
#endif

// ---------------- scratch (device globals; no allocation allowed) ----------
__device__ __nv_bfloat16 g_ahi[M_TOT * D];
__device__ __nv_bfloat16 g_alo[M_TOT * D];
__device__ __nv_bfloat16 g_whi[2 * D * D];   // transposed: [z][n][k]
__device__ __nv_bfloat16 g_wlo[2 * D * D];
__device__ float g_qk[M_TOT * D];            // rows 0-511: q, 512-767: k
__device__ float g_attn[NB * NT * NS];
__device__ float g_sal[NB * NS * NE];
__device__ float g_xw[M_TOT];                // [0,512): x.Wp1  [512,768): mem.Wp2

// ---------------- PTX helpers ---------------------------------------------
__device__ __forceinline__ uint32_t smem_u32(const void* p) {
    uint32_t a;
    asm("{ .reg .u64 t; cvta.to.shared.u64 t, %1; cvt.u32.u64 %0, t; }"
        : "=r"(a) : "l"(p));
    return a;
}
__device__ __forceinline__ uint32_t elect1() {
    uint32_t p;
    asm volatile("{\n\t.reg .pred p;\n\telect.sync _|p, 0xFFFFFFFF;\n\t"
                 "selp.b32 %0, 1, 0, p;\n\t}" : "=r"(p));
    return p;
}
#define MBARRIER_INIT(a, c) \
    asm volatile("mbarrier.init.shared.b64 [%0], %1;" :: "r"(a), "r"(c) : "memory")
#define MBARRIER_INVAL(a) \
    asm volatile("mbarrier.inval.shared.b64 [%0];" :: "r"(a) : "memory")
#define MBARRIER_WAIT_PARITY(mb, ph) do {                                        \
    uint32_t _m = (mb), _p = (ph), _d;                                           \
    asm volatile("{\n\t.reg .pred p;\n\t"                                        \
        "mbarrier.try_wait.parity.acquire.cta.shared::cta.b64 p, [%1], %2;\n\t"  \
        "selp.b32 %0, 1, 0, p;\n\t}" : "=r"(_d) : "r"(_m), "r"(_p) : "memory");  \
    if (!_d) {                                                                   \
        asm volatile("{\n\t.reg .pred P1;\n\t"                                   \
          "WL_%=:\n\t"                                                           \
          "mbarrier.try_wait.parity.acquire.cta.shared::cta.b64 P1, [%0], %1, 0x989680;\n\t" \
          "@P1 bra.uni WD_%=;\n\t"                                               \
          "bra.uni WL_%=;\n\t"                                                   \
          "WD_%=:\n\t}" :: "r"(_m), "r"(_p) : "memory");                         \
    }                                                                            \
} while (0)

#if HAS_TCGEN05
#define TCGEN05_ALLOC(sa, n) \
    asm volatile("tcgen05.alloc.cta_group::1.sync.aligned.shared::cta.b32 [%0], %1;" \
                 :: "r"((uint32_t)(sa)), "r"((uint32_t)(n)) : "memory")
#define TCGEN05_DEALLOC(t, n) \
    asm volatile("tcgen05.dealloc.cta_group::1.sync.aligned.b32 %0, %1;" :: "r"(t), "r"(n))
#define TCGEN05_RELINQ() \
    asm volatile("tcgen05.relinquish_alloc_permit.cta_group::1.sync.aligned;")
#define TCGEN05_COMMIT(mb) \
    asm volatile("tcgen05.commit.cta_group::1.mbarrier::arrive::one.shared::cluster.b64 [%0];" \
                 :: "r"((uint32_t)(mb)) : "memory")
#define TCGEN05_FENCE_AFTER() \
    asm volatile("tcgen05.fence::after_thread_sync;" ::: "memory")
#define TCGEN05_FENCE_BEFORE() \
    asm volatile("tcgen05.fence::before_thread_sync;" ::: "memory")
#define TCGEN05_WAIT_LD() asm volatile("tcgen05.wait::ld.sync.aligned;" ::: "memory")
#define FENCE_PROXY_ASYNC() \
    asm volatile("fence.proxy.async.shared::cta;" ::: "memory")
#define TCGEN05_LD_32X32B_X32(r, ta) \
    asm volatile( \
        "tcgen05.ld.sync.aligned.32x32b.x32.b32 " \
        "{%0, %1, %2, %3, %4, %5, %6, %7, " \
        " %8, %9, %10, %11, %12, %13, %14, %15, " \
        " %16, %17, %18, %19, %20, %21, %22, %23, " \
        " %24, %25, %26, %27, %28, %29, %30, %31}, [%32];" \
        : "=r"((r)[0]),  "=r"((r)[1]),  "=r"((r)[2]),  "=r"((r)[3]), \
          "=r"((r)[4]),  "=r"((r)[5]),  "=r"((r)[6]),  "=r"((r)[7]), \
          "=r"((r)[8]),  "=r"((r)[9]),  "=r"((r)[10]), "=r"((r)[11]), \
          "=r"((r)[12]), "=r"((r)[13]), "=r"((r)[14]), "=r"((r)[15]), \
          "=r"((r)[16]), "=r"((r)[17]), "=r"((r)[18]), "=r"((r)[19]), \
          "=r"((r)[20]), "=r"((r)[21]), "=r"((r)[22]), "=r"((r)[23]), \
          "=r"((r)[24]), "=r"((r)[25]), "=r"((r)[26]), "=r"((r)[27]), \
          "=r"((r)[28]), "=r"((r)[29]), "=r"((r)[30]), "=r"((r)[31]) \
        : "r"(ta))

__device__ __forceinline__ void mma_f16_ss(uint32_t d, uint64_t a, uint64_t b,
                                           uint32_t idesc, uint32_t en) {
    asm volatile("{\n\t.reg .pred p;\n\tsetp.ne.u32 p, %5, 0;\n\t"
        "tcgen05.mma.cta_group::1.kind::f16 [%0], %1, %2, %3, {%4,%4,%4,%4}, p;\n\t}"
        :: "r"(d), "l"(a), "l"(b), "r"(idesc), "r"(0u), "r"(en) : "memory");
}
#endif  // HAS_TCGEN05

#define SWZ(b) ((b) ^ (((b) >> 3) & 0x70))
static constexpr uint64_t DESC_BASE_SW128 =
    (uint64_t(2) << 61) | (uint64_t(1) << 46) | (uint64_t(64) << 32) | (uint64_t(1) << 16);
#define MAKE_DESC(a) (DESC_BASE_SW128 | ((uint64_t)((a) >> 4) & 0x3FFF))

// idesc: kind::f16, dtype=F32, atype=BF16, btype=BF16, N=128, M=128
static constexpr uint32_t GEMM_IDESC =
    (1u << 4) | (1u << 7) | (1u << 10) | ((128u / 8u) << 17) | ((128u / 16u) << 24);

__device__ __forceinline__ float warp_sum(float v) {
#pragma unroll
    for (int o = 16; o > 0; o >>= 1) v += __shfl_down_sync(0xffffffffu, v, o);
    return v;
}
__device__ __forceinline__ float warp_sum_all(float v) {
#pragma unroll
    for (int o = 16; o > 0; o >>= 1) v += __shfl_xor_sync(0xffffffffu, v, o);
    return v;
}
__device__ __forceinline__ float warp_max_all(float v) {
#pragma unroll
    for (int o = 16; o > 0; o >>= 1) v = fmaxf(v, __shfl_xor_sync(0xffffffffu, v, o));
    return v;
}

// ---------------------------------------------------------------------------
// fp32 -> bf16 hi/lo split of [x ; mem] into g_ahi/g_alo (768 x 1024)
// ---------------------------------------------------------------------------
__global__ __launch_bounds__(256) void cvt_inputs(
    const float* __restrict__ x, const float* __restrict__ mem)
{
    int i = blockIdx.x * 256 + threadIdx.x;        // float4 index, 196608 total
    const float4* src = (i < 131072) ? ((const float4*)x + i)
                                     : ((const float4*)mem + (i - 131072));
    float4 v = *src;
    int base = i * 4;
    float f[4] = {v.x, v.y, v.z, v.w};
#pragma unroll
    for (int j = 0; j < 4; j++) {
        __nv_bfloat16 h = __float2bfloat16(f[j]);
        g_ahi[base + j] = h;
        g_alo[base + j] = __float2bfloat16(f[j] - __bfloat162float(h));
    }
}

// ---------------------------------------------------------------------------
// Transpose + split W: g_whi/g_wlo[z][n][k] = split(W_z[k][n])
// ---------------------------------------------------------------------------
__global__ __launch_bounds__(256) void cvt_w(
    const float* __restrict__ Wq, const float* __restrict__ Wk)
{
    __shared__ float t[32][33];
    const float* W = blockIdx.z ? Wk : Wq;
    size_t zoff = (size_t)blockIdx.z * D * D;
    int n0 = blockIdx.x * 32, k0 = blockIdx.y * 32;
    int tx = threadIdx.x, ty = threadIdx.y;
#pragma unroll
    for (int j = 0; j < 4; j++)
        t[ty + j * 8][tx] = W[(size_t)(k0 + ty + j * 8) * D + n0 + tx];
    __syncthreads();
#pragma unroll
    for (int j = 0; j < 4; j++) {
        float v = t[tx][ty + j * 8];                 // = W[k0+tx][n0+ty+j*8]
        size_t o = zoff + (size_t)(n0 + ty + j * 8) * D + k0 + tx;
        __nv_bfloat16 h = __float2bfloat16(v);
        g_whi[o] = h;
        g_wlo[o] = __float2bfloat16(v - __bfloat162float(h));
    }
}

// ---------------------------------------------------------------------------
// prep_pgen: xw[r] = dot(x_row, Wp[0:D]) for r<512; dot(mem_row, Wp[D:2D]) else
// ---------------------------------------------------------------------------
__global__ __launch_bounds__(256) void prep_pgen(
    const float* __restrict__ x, const float* __restrict__ mem,
    const float* __restrict__ Wp)
{
    int row = blockIdx.x * 8 + (threadIdx.x >> 5);
    int lane = threadIdx.x & 31;
    const float* src = (row < 512) ? (x + (size_t)row * D)
                                   : (mem + (size_t)(row - 512) * D);
    const float* w = (row < 512) ? Wp : (Wp + D);
    float p = 0.f;
    for (int d = lane; d < D; d += 32) p += src[d] * w[d];
    p = warp_sum(p);
    if (lane == 0) g_xw[row] = p;
}

// ---------------------------------------------------------------------------
// GEMM: g_qk[m][n] = sum_k A[m][k] * W_z[k][n] + bias.  grid (8,6), 256 thr.
// Double-buffered (2 stages, one mbarrier per stage).
// ---------------------------------------------------------------------------
#define SM_MBAR0  0
#define SM_MBAR1  8
#define SM_TPTR   16
#define SM_STAGE  65536
#define SM_BASE   1024
#define SM_TOTAL  (SM_BASE + 2 * SM_STAGE)   // 132096

#if HAS_TCGEN05
__device__ __forceinline__ void load_tile(char* smem, int off,
                                          const __nv_bfloat16* __restrict__ src)
{
    int tid = threadIdx.x;
#pragma unroll
    for (int i = 0; i < 4; i++) {
        int idx = tid + i * 256;                    // 0..1023
        int row = idx >> 3, c8 = idx & 7;
        uint32_t b = row * 128 + c8 * 16;
        *(float4*)(smem + off + SWZ(b)) =
            *(const float4*)(src + (size_t)row * D + c8 * 8);
    }
}
#endif

__global__ __launch_bounds__(256, 1) void mma_gemm(
    const float* __restrict__ x, const float* __restrict__ mem,
    const float* __restrict__ Wq, const float* __restrict__ Wk,
    const float* __restrict__ bq, const float* __restrict__ bk)
{
    extern __shared__ char smem[];
    int tid = threadIdx.x;
    int tn = blockIdx.x, tm = blockIdx.y;
    int m0 = tm * 128, n0 = tn * 128;

#if HAS_TCGEN05
    (void)x; (void)mem; (void)Wq; (void)Wk;
    uint32_t sb = smem_u32(smem);
    int wid = tid >> 5, lane = tid & 31;
    int z = (tm >= 4);

    const __nv_bfloat16* ahi = g_ahi + (size_t)m0 * D;
    const __nv_bfloat16* alo = g_alo + (size_t)m0 * D;
    const __nv_bfloat16* bhi = g_whi + (size_t)z * D * D + (size_t)n0 * D;
    const __nv_bfloat16* blo = g_wlo + (size_t)z * D * D + (size_t)n0 * D;

    if (wid == 0) TCGEN05_ALLOC(sb + SM_TPTR, 128);
    if (tid == 0) { MBARRIER_INIT(sb + SM_MBAR0, 1); MBARRIER_INIT(sb + SM_MBAR1, 1); }
    __syncthreads();
    uint32_t tmem;
    asm volatile("ld.shared.b32 %0, [%1];" : "=r"(tmem) : "r"(sb + SM_TPTR));

    for (int c = 0; c < 16; c++) {
        int stg = c & 1;
        uint32_t mb = sb + (stg ? SM_MBAR1 : SM_MBAR0);
        if (c >= 2) MBARRIER_WAIT_PARITY(mb, ((c >> 1) - 1) & 1);
        int base = SM_BASE + stg * SM_STAGE;
        load_tile(smem, base,         ahi + c * 64);
        load_tile(smem, base + 16384, alo + c * 64);
        load_tile(smem, base + 32768, bhi + c * 64);
        load_tile(smem, base + 49152, blo + c * 64);
        __syncthreads();
        if (wid == 0 && elect1()) {
            FENCE_PROXY_ASYNC();
            uint64_t dah = MAKE_DESC(sb + base);
            uint64_t dal = MAKE_DESC(sb + base + 16384);
            uint64_t dbh = MAKE_DESC(sb + base + 32768);
            uint64_t dbl = MAKE_DESC(sb + base + 49152);
#pragma unroll
            for (int s = 0; s < 4; s++) {
                uint64_t o = s * 2;
                mma_f16_ss(tmem, dah + o, dbh + o, GEMM_IDESC, !(c == 0 && s == 0));
                mma_f16_ss(tmem, dah + o, dbl + o, GEMM_IDESC, 1u);
                mma_f16_ss(tmem, dal + o, dbh + o, GEMM_IDESC, 1u);
            }
            TCGEN05_COMMIT(mb);
        }
    }
    // 8 commits on each mbar; wait phase 7 (parity 1) on both.
    MBARRIER_WAIT_PARITY(sb + SM_MBAR0, 1);
    MBARRIER_WAIT_PARITY(sb + SM_MBAR1, 1);
    TCGEN05_FENCE_AFTER();

    if (wid < 4) {
        uint32_t dr[128];
#pragma unroll
        for (int b = 0; b < 128; b += 32) TCGEN05_LD_32X32B_X32(dr + b, tmem + b);
        TCGEN05_WAIT_LD();
        TCGEN05_FENCE_BEFORE();
        int m = m0 + wid * 32 + lane;
        const float* bias = (m < 512) ? bq : bk;
        float* crow = g_qk + (size_t)m * D + n0;
#pragma unroll 8
        for (int cc = 0; cc < 128; cc++)
            crow[cc] = __uint_as_float(dr[cc]) + __ldg(&bias[n0 + cc]);
    }
    __syncthreads();
    if (tid == 0) { MBARRIER_INVAL(sb + SM_MBAR0); MBARRIER_INVAL(sb + SM_MBAR1); }
    __syncthreads();
    if (wid == 0) {
        TCGEN05_RELINQ();
        TCGEN05_DEALLOC(tmem, 128);
    }
#else
    // ---------------- SIMT fp32 fallback: 128x128 tile, BK=16, 8x8 micro ---
    float* As = (float*)smem;                    // [16][132] transposed A
    float* Bs = (float*)(smem + 16 * 132 * 4);   // [16][128]
    const float* Asrc = (m0 < 512) ? (x + (size_t)m0 * D)
                                   : (mem + (size_t)(m0 - 512) * D);
    const float* W = (m0 < 512) ? Wq : Wk;
    const float* bias = (m0 < 512) ? bq : bk;
    int tr = tid >> 4, tc = tid & 15;

    float acc[8][8];
#pragma unroll
    for (int i = 0; i < 8; i++)
#pragma unroll
        for (int j = 0; j < 8; j++) acc[i][j] = 0.f;

    for (int k0 = 0; k0 < D; k0 += 16) {
#pragma unroll
        for (int i = 0; i < 2; i++) {
            int f4 = tid * 2 + i;
            int row = f4 >> 2;
            int c4 = (f4 & 3) * 4;
            float4 v = *(const float4*)(Asrc + (size_t)row * D + k0 + c4);
            As[(c4 + 0) * 132 + row] = v.x;
            As[(c4 + 1) * 132 + row] = v.y;
            As[(c4 + 2) * 132 + row] = v.z;
            As[(c4 + 3) * 132 + row] = v.w;
        }
#pragma unroll
        for (int i = 0; i < 2; i++) {
            int f4 = tid * 2 + i;
            int row = f4 >> 5;
            int cc = (f4 & 31) * 4;
            *(float4*)(Bs + row * 128 + cc) =
                *(const float4*)(W + (size_t)(k0 + row) * D + n0 + cc);
        }
        __syncthreads();
#pragma unroll
        for (int kk = 0; kk < 16; kk++) {
            float a[8], bb[8];
#pragma unroll
            for (int i = 0; i < 8; i++) a[i] = As[kk * 132 + tr * 8 + i];
#pragma unroll
            for (int j = 0; j < 8; j++) bb[j] = Bs[kk * 128 + tc * 8 + j];
#pragma unroll
            for (int i = 0; i < 8; i++)
#pragma unroll
                for (int j = 0; j < 8; j++) acc[i][j] += a[i] * bb[j];
        }
        __syncthreads();
    }
#pragma unroll
    for (int i = 0; i < 8; i++) {
        int m = m0 + tr * 8 + i;
        float* crow = g_qk + (size_t)m * D + n0 + tc * 8;
#pragma unroll
        for (int j = 0; j < 8; j++) crow[j] = acc[i][j] + bias[n0 + tc * 8 + j];
    }
#endif
}

// ---------------------------------------------------------------------------
// attn2: grid (8 t-tiles, 8 b), 256 threads. k[b] transposed in smem
// (ksT[d][s], stride 33). Warp w handles t = tt*8 + w, lane = s.
// scores -> softmax (shfl) -> g_attn + p_gen (via precomputed xw/mw).
// ---------------------------------------------------------------------------
#define KST_STRIDE 33
#define ATTN_SMEM (D * KST_STRIDE * 4)   // 135168

__global__ __launch_bounds__(256, 1) void attn2(
    const float* __restrict__ bpv, float* __restrict__ out)
{
    extern __shared__ float ksT[];       // [D][33]
    int tt = blockIdx.x, b = blockIdx.y;
    int tid = threadIdx.x;
    int w = tid >> 5, lane = tid & 31;

    // load k[b] (g_qk rows 512 + b*32 ..) transposed
    {
        int s = tid >> 3, dg = tid & 7;
        const float* krow = g_qk + (size_t)(512 + b * NS + s) * D;
#pragma unroll
        for (int j = 0; j < 32; j++) {
            int d0 = (dg + j * 8) * 4;
            float4 v = *(const float4*)(krow + d0);
            ksT[(d0 + 0) * KST_STRIDE + s] = v.x;
            ksT[(d0 + 1) * KST_STRIDE + s] = v.y;
            ksT[(d0 + 2) * KST_STRIDE + s] = v.z;
            ksT[(d0 + 3) * KST_STRIDE + s] = v.w;
        }
    }
    __syncthreads();

    int t = tt * 8 + w;
    int bt = b * NT + t;
    const float* qrow = g_qk + (size_t)bt * D;

    float acc = 0.f;
#pragma unroll 4
    for (int d0 = 0; d0 < D; d0 += 4) {
        float4 q4 = *(const float4*)(qrow + d0);     // uniform within warp
        float k0 = ksT[(d0 + 0) * KST_STRIDE + lane];
        float k1 = ksT[(d0 + 1) * KST_STRIDE + lane];
        float k2 = ksT[(d0 + 2) * KST_STRIDE + lane];
        float k3 = ksT[(d0 + 3) * KST_STRIDE + lane];
        acc += q4.x * k0 + q4.y * k1 + q4.z * k2 + q4.w * k3;
    }
    float sc = acc * 0.03125f;                       // / sqrt(1024)
    float m = warp_max_all(sc);
    float e = expf(sc - m);
    float sum = warp_sum_all(e);
    float a = e / sum;
    g_attn[(size_t)bt * NS + lane] = a;

    float mw = g_xw[512 + b * NS + lane];
    float dot = warp_sum_all(a * mw);
    if (lane == 0) {
        float v = g_xw[bt] + dot + bpv[0];
        float zz = (v - 0.5f) * 10.f;
        out[bt] = 1.f / (1.f + expf(-zz));
    }
}

// ---------------------------------------------------------------------------
// Per (b,s): salience softmax; last-wins dedup of duplicate ids.
// ---------------------------------------------------------------------------
__global__ __launch_bounds__(128) void sal_kernel(
    const float* __restrict__ x, const float* __restrict__ emb, const int* __restrict__ ids)
{
    int bs = blockIdx.x;
    int b = bs >> 5;
    int tid = threadIdx.x, lane = tid & 31, w = tid >> 5;

    __shared__ float dl[D];
    __shared__ float sc[NE];
    __shared__ int id_s[NE];

    const float* xl = x + (size_t)(b * NT + NT - 1) * D;
    for (int i = tid; i < D; i += 128) dl[i] = xl[i];
    if (tid < NE) id_s[tid] = ids[(size_t)bs * NE + tid];
    __syncthreads();

#pragma unroll
    for (int j = 0; j < 4; j++) {
        int e = w * 4 + j;
        const float* er = emb + (size_t)id_s[e] * D;
        float p = 0.f;
        for (int d = lane; d < D; d += 32) p += dl[d] * er[d];
        p = warp_sum(p);
        if (lane == 0) sc[e] = p;
    }
    __syncthreads();

    if (tid == 0) {
        float m = sc[0];
        for (int e = 1; e < NE; e++) m = fmaxf(m, sc[e]);
        float a[NE];
        float sum = 0.f;
        for (int e = 0; e < NE; e++) { a[e] = expf(sc[e] - m); sum += a[e]; }
        float inv = 1.f / sum;
        for (int e = 0; e < NE; e++) {
            float val = a[e] * inv;
            for (int e2 = e + 1; e2 < NE; e2++)
                if (id_s[e2] == id_s[e]) { val = 0.f; break; }
            g_sal[(size_t)bs * NE + e] = val;
        }
    }
}

// ---------------------------------------------------------------------------
// fused_out: block bt zeros its 50257-float row, then atomicAdds its 512
// contributions (L2-hit, just-written lines). Replaces memset + scatter.
// ---------------------------------------------------------------------------
__global__ __launch_bounds__(256) void fused_out(
    const int* __restrict__ ids, float* __restrict__ out)
{
    int bt = blockIdx.x;
    int b = bt >> 6;
    int tid = threadIdx.x;

    __shared__ float att[NS];
    __shared__ float sal_s[NS * NE];
    __shared__ int ids_s[NS * NE];

    if (tid < NS) att[tid] = g_attn[(size_t)bt * NS + tid];
    for (int i = tid; i < NS * NE; i += 256) {
        sal_s[i] = g_sal[(size_t)b * NS * NE + i];
        ids_s[i] = ids[(size_t)b * NS * NE + i];
    }

    float* base = out + 512 + (size_t)bt * NV;
    int pad = (4 - ((512 + bt * (NV & 3)) & 3)) & 3;   // (start elem) mod 4
    // start elem = 512 + bt*NV; 512%4==0, NV%4==1 -> mod4 = bt&3
    pad = (4 - (bt & 3)) & 3;
    for (int i = tid; i < pad; i += 256) base[i] = 0.f;
    int n4 = (NV - pad) >> 2;
    float4* b4 = (float4*)(base + pad);
    float4 z4 = make_float4(0.f, 0.f, 0.f, 0.f);
    for (int i = tid; i < n4; i += 256) b4[i] = z4;
    int done = pad + n4 * 4;
    for (int i = done + tid; i < NV; i += 256) base[i] = 0.f;
    __syncthreads();

    for (int i = tid; i < NS * NE; i += 256) {
        int s = i >> 4;
        float val = att[s] * sal_s[i];
        if (val != 0.f) atomicAdd(base + ids_s[i], val);
    }
}

// ---------------------------------------------------------------------------
extern "C" void kernel_launch(void* const* d_in, const int* in_sizes, int n_in,
                              void* d_out, int out_size)
{
    const float* x   = (const float*)d_in[0];
    const float* mem = (const float*)d_in[1];
    const float* emb = (const float*)d_in[2];
    const int*   ids = (const int*)d_in[3];
    const float* Wq  = (const float*)d_in[4];
    const float* bq  = (const float*)d_in[5];
    const float* Wk  = (const float*)d_in[6];
    const float* bk  = (const float*)d_in[7];
    const float* Wp  = (const float*)d_in[8];
    const float* bp  = (const float*)d_in[9];
    float* out = (float*)d_out;

    cudaFuncSetAttribute(mma_gemm, cudaFuncAttributeMaxDynamicSharedMemorySize, SM_TOTAL);
    cudaFuncSetAttribute(attn2, cudaFuncAttributeMaxDynamicSharedMemorySize, ATTN_SMEM);

    prep_pgen<<<96, 256>>>(x, mem, Wp);
    cvt_inputs<<<768, 256>>>(x, mem);
    cvt_w<<<dim3(32, 32, 2), dim3(32, 8)>>>(Wq, Wk);
    mma_gemm<<<dim3(8, 6), 256, SM_TOTAL>>>(x, mem, Wq, Wk, bq, bk);
    sal_kernel<<<NB * NS, 128>>>(x, emb, ids);
    attn2<<<dim3(8, 8), 256, ATTN_SMEM>>>(bp, out);
    fused_out<<<NB * NT, 256>>>(ids, out);
}

// round 5
// speedup vs baseline: 1.2117x; 1.2117x over previous
#include <cuda_runtime.h>
#include <cuda_bf16.h>
#include <cstdint>

#define D 1024
#define NB 8
#define NT 64
#define NS 32
#define NE 16
#define NV 50257
#define M_TOT 768          // 512 q rows + 256 k rows

// tcgen05 only exists in the arch-SPECIFIC (sm_103a) device pass.
#if defined(__CUDA_ARCH_FEAT_SM103_ALL) || \
    (defined(__CUDA_ARCH_SPECIFIC__) && (__CUDA_ARCH_SPECIFIC__ == 1030))
#define HAS_TCGEN05 1
#else
#define HAS_TCGEN05 0
#endif

// ---------------- scratch (device globals; no allocation allowed) ----------
__device__ __nv_bfloat16 g_ahi[M_TOT * D];
__device__ __nv_bfloat16 g_alo[M_TOT * D];
__device__ __nv_bfloat16 g_whi[2 * D * D];   // transposed: [z][n][k]
__device__ __nv_bfloat16 g_wlo[2 * D * D];
__device__ float g_qk[M_TOT * D];            // rows 0-511: q, 512-767: k
__device__ float g_attn[NB * NT * NS];
__device__ float g_sal[NB * NS * NE];
__device__ float g_xw[M_TOT];                // [0,512): x.Wp1  [512,768): mem.Wp2

// ---------------- PTX helpers ---------------------------------------------
__device__ __forceinline__ uint32_t smem_u32(const void* p) {
    uint32_t a;
    asm("{ .reg .u64 t; cvta.to.shared.u64 t, %1; cvt.u32.u64 %0, t; }"
        : "=r"(a) : "l"(p));
    return a;
}
__device__ __forceinline__ uint32_t elect1() {
    uint32_t p;
    asm volatile("{\n\t.reg .pred p;\n\telect.sync _|p, 0xFFFFFFFF;\n\t"
                 "selp.b32 %0, 1, 0, p;\n\t}" : "=r"(p));
    return p;
}
#define MBARRIER_INIT(a, c) \
    asm volatile("mbarrier.init.shared.b64 [%0], %1;" :: "r"(a), "r"(c) : "memory")
#define MBARRIER_INVAL(a) \
    asm volatile("mbarrier.inval.shared.b64 [%0];" :: "r"(a) : "memory")
#define MBARRIER_WAIT_PARITY(mb, ph) do {                                        \
    uint32_t _m = (mb), _p = (ph), _d;                                           \
    asm volatile("{\n\t.reg .pred p;\n\t"                                        \
        "mbarrier.try_wait.parity.acquire.cta.shared::cta.b64 p, [%1], %2;\n\t"  \
        "selp.b32 %0, 1, 0, p;\n\t}" : "=r"(_d) : "r"(_m), "r"(_p) : "memory");  \
    if (!_d) {                                                                   \
        asm volatile("{\n\t.reg .pred P1;\n\t"                                   \
          "WL_%=:\n\t"                                                           \
          "mbarrier.try_wait.parity.acquire.cta.shared::cta.b64 P1, [%0], %1, 0x989680;\n\t" \
          "@P1 bra.uni WD_%=;\n\t"                                               \
          "bra.uni WL_%=;\n\t"                                                   \
          "WD_%=:\n\t}" :: "r"(_m), "r"(_p) : "memory");                         \
    }                                                                            \
} while (0)

#define CP_ASYNC16(dst, src) \
    asm volatile("cp.async.cg.shared.global [%0], [%1], 16;" \
                 :: "r"(dst), "l"(src) : "memory")
#define CP_COMMIT() asm volatile("cp.async.commit_group;" ::: "memory")
#define CP_WAIT2()  asm volatile("cp.async.wait_group 2;" ::: "memory")
#define CP_WAIT0()  asm volatile("cp.async.wait_group 0;" ::: "memory")

#if HAS_TCGEN05
#define TCGEN05_ALLOC(sa, n) \
    asm volatile("tcgen05.alloc.cta_group::1.sync.aligned.shared::cta.b32 [%0], %1;" \
                 :: "r"((uint32_t)(sa)), "r"((uint32_t)(n)) : "memory")
#define TCGEN05_DEALLOC(t, n) \
    asm volatile("tcgen05.dealloc.cta_group::1.sync.aligned.b32 %0, %1;" :: "r"(t), "r"(n))
#define TCGEN05_RELINQ() \
    asm volatile("tcgen05.relinquish_alloc_permit.cta_group::1.sync.aligned;")
#define TCGEN05_COMMIT(mb) \
    asm volatile("tcgen05.commit.cta_group::1.mbarrier::arrive::one.shared::cluster.b64 [%0];" \
                 :: "r"((uint32_t)(mb)) : "memory")
#define TCGEN05_FENCE_AFTER() \
    asm volatile("tcgen05.fence::after_thread_sync;" ::: "memory")
#define TCGEN05_FENCE_BEFORE() \
    asm volatile("tcgen05.fence::before_thread_sync;" ::: "memory")
#define TCGEN05_WAIT_LD() asm volatile("tcgen05.wait::ld.sync.aligned;" ::: "memory")
#define FENCE_PROXY_ASYNC() \
    asm volatile("fence.proxy.async.shared::cta;" ::: "memory")
#define TCGEN05_LD_32X32B_X32(r, ta) \
    asm volatile( \
        "tcgen05.ld.sync.aligned.32x32b.x32.b32 " \
        "{%0, %1, %2, %3, %4, %5, %6, %7, " \
        " %8, %9, %10, %11, %12, %13, %14, %15, " \
        " %16, %17, %18, %19, %20, %21, %22, %23, " \
        " %24, %25, %26, %27, %28, %29, %30, %31}, [%32];" \
        : "=r"((r)[0]),  "=r"((r)[1]),  "=r"((r)[2]),  "=r"((r)[3]), \
          "=r"((r)[4]),  "=r"((r)[5]),  "=r"((r)[6]),  "=r"((r)[7]), \
          "=r"((r)[8]),  "=r"((r)[9]),  "=r"((r)[10]), "=r"((r)[11]), \
          "=r"((r)[12]), "=r"((r)[13]), "=r"((r)[14]), "=r"((r)[15]), \
          "=r"((r)[16]), "=r"((r)[17]), "=r"((r)[18]), "=r"((r)[19]), \
          "=r"((r)[20]), "=r"((r)[21]), "=r"((r)[22]), "=r"((r)[23]), \
          "=r"((r)[24]), "=r"((r)[25]), "=r"((r)[26]), "=r"((r)[27]), \
          "=r"((r)[28]), "=r"((r)[29]), "=r"((r)[30]), "=r"((r)[31]) \
        : "r"(ta))

__device__ __forceinline__ void mma_f16_ss(uint32_t d, uint64_t a, uint64_t b,
                                           uint32_t idesc, uint32_t en) {
    asm volatile("{\n\t.reg .pred p;\n\tsetp.ne.u32 p, %5, 0;\n\t"
        "tcgen05.mma.cta_group::1.kind::f16 [%0], %1, %2, %3, {%4,%4,%4,%4}, p;\n\t}"
        :: "r"(d), "l"(a), "l"(b), "r"(idesc), "r"(0u), "r"(en) : "memory");
}
#endif  // HAS_TCGEN05

#define SWZ(b) ((b) ^ (((b) >> 3) & 0x70))
static constexpr uint64_t DESC_BASE_SW128 =
    (uint64_t(2) << 61) | (uint64_t(1) << 46) | (uint64_t(64) << 32) | (uint64_t(1) << 16);
#define MAKE_DESC(a) (DESC_BASE_SW128 | ((uint64_t)((a) >> 4) & 0x3FFF))

// idesc: kind::f16, dtype=F32, atype=BF16, btype=BF16, N=128, M=128
static constexpr uint32_t GEMM_IDESC =
    (1u << 4) | (1u << 7) | (1u << 10) | ((128u / 8u) << 17) | ((128u / 16u) << 24);

__device__ __forceinline__ float warp_sum(float v) {
#pragma unroll
    for (int o = 16; o > 0; o >>= 1) v += __shfl_down_sync(0xffffffffu, v, o);
    return v;
}
__device__ __forceinline__ float warp_sum_all(float v) {
#pragma unroll
    for (int o = 16; o > 0; o >>= 1) v += __shfl_xor_sync(0xffffffffu, v, o);
    return v;
}
__device__ __forceinline__ float warp_max_all(float v) {
#pragma unroll
    for (int o = 16; o > 0; o >>= 1) v = fmaxf(v, __shfl_xor_sync(0xffffffffu, v, o));
    return v;
}

// ---------------------------------------------------------------------------
// prep_everything: one kernel, 3168 blocks x 256 threads.
//  [0,768)      : fp32 -> bf16 hi/lo split of [x ; mem]
//  [768,864)    : p_gen partial dots xw
//  [864,1120)   : salience softmax (per b,s)
//  [1120,3168)  : W transpose + hi/lo split
// ---------------------------------------------------------------------------
__global__ __launch_bounds__(256) void prep_everything(
    const float* __restrict__ x, const float* __restrict__ mem,
    const float* __restrict__ emb, const int* __restrict__ ids,
    const float* __restrict__ Wq, const float* __restrict__ Wk,
    const float* __restrict__ Wp)
{
    __shared__ float shbuf[1100];      // union: sal dl[1024]+sc[16] / cvt_w t[32][33]
    __shared__ int id_s[NE];
    int bid = blockIdx.x;
    int tid = threadIdx.x;

    if (bid < 768) {
        // ---- cvt_inputs ----
        int i = bid * 256 + tid;
        const float4* src = (i < 131072) ? ((const float4*)x + i)
                                         : ((const float4*)mem + (i - 131072));
        float4 v = *src;
        int base = i * 4;
        float f[4] = {v.x, v.y, v.z, v.w};
#pragma unroll
        for (int j = 0; j < 4; j++) {
            __nv_bfloat16 h = __float2bfloat16(f[j]);
            g_ahi[base + j] = h;
            g_alo[base + j] = __float2bfloat16(f[j] - __bfloat162float(h));
        }
    } else if (bid < 864) {
        // ---- prep_pgen ----
        int row = (bid - 768) * 8 + (tid >> 5);
        int lane = tid & 31;
        const float* src = (row < 512) ? (x + (size_t)row * D)
                                       : (mem + (size_t)(row - 512) * D);
        const float* w = (row < 512) ? Wp : (Wp + D);
        float p = 0.f;
        for (int d = lane; d < D; d += 32) p += src[d] * w[d];
        p = warp_sum(p);
        if (lane == 0) g_xw[row] = p;
    } else if (bid < 1120) {
        // ---- salience ----
        int bs = bid - 864;
        int b = bs >> 5;
        int lane = tid & 31, w = tid >> 5;
        float* dl = shbuf;
        float* sc = shbuf + 1024;

        const float* xl = x + (size_t)(b * NT + NT - 1) * D;
        for (int i = tid; i < D; i += 256) dl[i] = xl[i];
        if (tid < NE) id_s[tid] = ids[(size_t)bs * NE + tid];
        __syncthreads();

#pragma unroll
        for (int j = 0; j < 2; j++) {
            int e = w * 2 + j;
            const float* er = emb + (size_t)id_s[e] * D;
            float p = 0.f;
            for (int d = lane; d < D; d += 32) p += dl[d] * er[d];
            p = warp_sum(p);
            if (lane == 0) sc[e] = p;
        }
        __syncthreads();

        if (tid == 0) {
            float m = sc[0];
            for (int e = 1; e < NE; e++) m = fmaxf(m, sc[e]);
            float a[NE];
            float sum = 0.f;
            for (int e = 0; e < NE; e++) { a[e] = expf(sc[e] - m); sum += a[e]; }
            float inv = 1.f / sum;
            for (int e = 0; e < NE; e++) {
                float val = a[e] * inv;
                for (int e2 = e + 1; e2 < NE; e2++)
                    if (id_s[e2] == id_s[e]) { val = 0.f; break; }
                g_sal[(size_t)bs * NE + e] = val;
            }
        }
    } else {
        // ---- cvt_w (transpose + split) ----
        int zz = bid - 1120;                  // 0..2047
        int z = zz >> 10;
        int rem = zz & 1023;
        int k0 = (rem >> 5) * 32, n0 = (rem & 31) * 32;
        const float* W = z ? Wk : Wq;
        size_t zoff = (size_t)z * D * D;
        float (*t)[33] = (float(*)[33])shbuf;
        int tx = tid & 31, ty = tid >> 5;
#pragma unroll
        for (int j = 0; j < 4; j++)
            t[ty + j * 8][tx] = W[(size_t)(k0 + ty + j * 8) * D + n0 + tx];
        __syncthreads();
#pragma unroll
        for (int j = 0; j < 4; j++) {
            float v = t[tx][ty + j * 8];
            size_t o = zoff + (size_t)(n0 + ty + j * 8) * D + k0 + tx;
            __nv_bfloat16 h = __float2bfloat16(v);
            g_whi[o] = h;
            g_wlo[o] = __float2bfloat16(v - __bfloat162float(h));
        }
    }
}

// ---------------------------------------------------------------------------
// GEMM: g_qk[m][n] = sum_k A[m][k] * W_z[k][n] + bias.  grid (8,6), 256 thr.
// 3-stage cp.async pipeline; per-stage mbarriers gate stage reuse.
// ---------------------------------------------------------------------------
#define SM_MBAR0  0
#define SM_MBAR1  8
#define SM_MBAR2  16
#define SM_TPTR   32
#define SM_STAGE  65536
#define SM_BASE   1024
#define SM_TOTAL  (SM_BASE + 3 * SM_STAGE)   // 197632

#if HAS_TCGEN05
__device__ __forceinline__ void load_tile_async(uint32_t soff,
                                                const __nv_bfloat16* __restrict__ src)
{
    int tid = threadIdx.x;
#pragma unroll
    for (int i = 0; i < 4; i++) {
        int idx = tid + i * 256;                    // 0..1023
        int row = idx >> 3, c8 = idx & 7;
        uint32_t b = row * 128 + c8 * 16;
        CP_ASYNC16(soff + SWZ(b), (const char*)(src + (size_t)row * D + c8 * 8));
    }
}
#endif

__global__ __launch_bounds__(256, 1) void mma_gemm(
    const float* __restrict__ x, const float* __restrict__ mem,
    const float* __restrict__ Wq, const float* __restrict__ Wk,
    const float* __restrict__ bq, const float* __restrict__ bk)
{
    extern __shared__ char smem[];
    int tid = threadIdx.x;
    int tn = blockIdx.x, tm = blockIdx.y;
    int m0 = tm * 128, n0 = tn * 128;

#if HAS_TCGEN05
    (void)x; (void)mem; (void)Wq; (void)Wk;
    uint32_t sb = smem_u32(smem);
    int wid = tid >> 5, lane = tid & 31;
    int z = (tm >= 4);

    const __nv_bfloat16* ahi = g_ahi + (size_t)m0 * D;
    const __nv_bfloat16* alo = g_alo + (size_t)m0 * D;
    const __nv_bfloat16* bhi = g_whi + (size_t)z * D * D + (size_t)n0 * D;
    const __nv_bfloat16* blo = g_wlo + (size_t)z * D * D + (size_t)n0 * D;

    if (wid == 0) TCGEN05_ALLOC(sb + SM_TPTR, 128);
    if (tid == 0) {
        MBARRIER_INIT(sb + SM_MBAR0, 1);
        MBARRIER_INIT(sb + SM_MBAR1, 1);
        MBARRIER_INIT(sb + SM_MBAR2, 1);
    }
    __syncthreads();
    uint32_t tmem;
    asm volatile("ld.shared.b32 %0, [%1];" : "=r"(tmem) : "r"(sb + SM_TPTR));

    // prologue: chunks 0,1,2
#pragma unroll
    for (int c = 0; c < 3; c++) {
        uint32_t so = sb + SM_BASE + c * SM_STAGE;
        load_tile_async(so,         ahi + c * 64);
        load_tile_async(so + 16384, alo + c * 64);
        load_tile_async(so + 32768, bhi + c * 64);
        load_tile_async(so + 49152, blo + c * 64);
        CP_COMMIT();
    }

    for (int c = 0; c < 16; c++) {
        int stg = c - (c / 3) * 3;
        uint32_t so = sb + SM_BASE + stg * SM_STAGE;
        uint32_t mb = sb + stg * 8;                 // SM_MBAR{0,1,2}
        CP_WAIT2();
        __syncthreads();                            // chunk c visible to CTA
        if (wid == 0 && elect1()) {
            FENCE_PROXY_ASYNC();
            uint64_t dah = MAKE_DESC(so);
            uint64_t dal = MAKE_DESC(so + 16384);
            uint64_t dbh = MAKE_DESC(so + 32768);
            uint64_t dbl = MAKE_DESC(so + 49152);
#pragma unroll
            for (int s = 0; s < 4; s++) {
                uint64_t o = s * 2;
                mma_f16_ss(tmem, dah + o, dbh + o, GEMM_IDESC, !(c == 0 && s == 0));
                mma_f16_ss(tmem, dah + o, dbl + o, GEMM_IDESC, 1u);
                mma_f16_ss(tmem, dal + o, dbh + o, GEMM_IDESC, 1u);
            }
            TCGEN05_COMMIT(mb);
        }
        if (c <= 12) {
            // refill stage stg with chunk c+3 once MMA(c) (commit #(c/3+1)) done
            MBARRIER_WAIT_PARITY(mb, (c / 3) & 1);
            int cn = c + 3;
            load_tile_async(so,         ahi + cn * 64);
            load_tile_async(so + 16384, alo + cn * 64);
            load_tile_async(so + 32768, bhi + cn * 64);
            load_tile_async(so + 49152, blo + cn * 64);
            CP_COMMIT();
        }
    }
    CP_WAIT0();
    // stage0: 6 commits -> parity 1; stages 1,2: 5 commits -> parity 0
    MBARRIER_WAIT_PARITY(sb + SM_MBAR0, 1);
    MBARRIER_WAIT_PARITY(sb + SM_MBAR1, 0);
    MBARRIER_WAIT_PARITY(sb + SM_MBAR2, 0);
    TCGEN05_FENCE_AFTER();

    if (wid < 4) {
        uint32_t dr[128];
#pragma unroll
        for (int b = 0; b < 128; b += 32) TCGEN05_LD_32X32B_X32(dr + b, tmem + b);
        TCGEN05_WAIT_LD();
        TCGEN05_FENCE_BEFORE();
        int m = m0 + wid * 32 + lane;
        const float* bias = (m < 512) ? bq : bk;
        float* crow = g_qk + (size_t)m * D + n0;
#pragma unroll 8
        for (int cc = 0; cc < 128; cc++)
            crow[cc] = __uint_as_float(dr[cc]) + __ldg(&bias[n0 + cc]);
    }
    __syncthreads();
    if (tid == 0) {
        MBARRIER_INVAL(sb + SM_MBAR0);
        MBARRIER_INVAL(sb + SM_MBAR1);
        MBARRIER_INVAL(sb + SM_MBAR2);
    }
    __syncthreads();
    if (wid == 0) {
        TCGEN05_RELINQ();
        TCGEN05_DEALLOC(tmem, 128);
    }
#else
    // ---------------- SIMT fp32 fallback: 128x128 tile, BK=16, 8x8 micro ---
    float* As = (float*)smem;                    // [16][132] transposed A
    float* Bs = (float*)(smem + 16 * 132 * 4);   // [16][128]
    const float* Asrc = (m0 < 512) ? (x + (size_t)m0 * D)
                                   : (mem + (size_t)(m0 - 512) * D);
    const float* W = (m0 < 512) ? Wq : Wk;
    const float* bias = (m0 < 512) ? bq : bk;
    int tr = tid >> 4, tc = tid & 15;

    float acc[8][8];
#pragma unroll
    for (int i = 0; i < 8; i++)
#pragma unroll
        for (int j = 0; j < 8; j++) acc[i][j] = 0.f;

    for (int k0 = 0; k0 < D; k0 += 16) {
#pragma unroll
        for (int i = 0; i < 2; i++) {
            int f4 = tid * 2 + i;
            int row = f4 >> 2;
            int c4 = (f4 & 3) * 4;
            float4 v = *(const float4*)(Asrc + (size_t)row * D + k0 + c4);
            As[(c4 + 0) * 132 + row] = v.x;
            As[(c4 + 1) * 132 + row] = v.y;
            As[(c4 + 2) * 132 + row] = v.z;
            As[(c4 + 3) * 132 + row] = v.w;
        }
#pragma unroll
        for (int i = 0; i < 2; i++) {
            int f4 = tid * 2 + i;
            int row = f4 >> 5;
            int cc = (f4 & 31) * 4;
            *(float4*)(Bs + row * 128 + cc) =
                *(const float4*)(W + (size_t)(k0 + row) * D + n0 + cc);
        }
        __syncthreads();
#pragma unroll
        for (int kk = 0; kk < 16; kk++) {
            float a[8], bb[8];
#pragma unroll
            for (int i = 0; i < 8; i++) a[i] = As[kk * 132 + tr * 8 + i];
#pragma unroll
            for (int j = 0; j < 8; j++) bb[j] = Bs[kk * 128 + tc * 8 + j];
#pragma unroll
            for (int i = 0; i < 8; i++)
#pragma unroll
                for (int j = 0; j < 8; j++) acc[i][j] += a[i] * bb[j];
        }
        __syncthreads();
    }
#pragma unroll
    for (int i = 0; i < 8; i++) {
        int m = m0 + tr * 8 + i;
        float* crow = g_qk + (size_t)m * D + n0 + tc * 8;
#pragma unroll
        for (int j = 0; j < 8; j++) crow[j] = acc[i][j] + bias[n0 + tc * 8 + j];
    }
#endif
}

// ---------------------------------------------------------------------------
// attn2: grid (8 t-tiles, 8 b), 256 threads. k[b] transposed in smem.
// ---------------------------------------------------------------------------
#define KST_STRIDE 33
#define ATTN_SMEM (D * KST_STRIDE * 4)   // 135168

__global__ __launch_bounds__(256, 1) void attn2(
    const float* __restrict__ bpv, float* __restrict__ out)
{
    extern __shared__ float ksT[];       // [D][33]
    int tt = blockIdx.x, b = blockIdx.y;
    int tid = threadIdx.x;
    int w = tid >> 5, lane = tid & 31;

    {
        int s = tid >> 3, dg = tid & 7;
        const float* krow = g_qk + (size_t)(512 + b * NS + s) * D;
#pragma unroll
        for (int j = 0; j < 32; j++) {
            int d0 = (dg + j * 8) * 4;
            float4 v = *(const float4*)(krow + d0);
            ksT[(d0 + 0) * KST_STRIDE + s] = v.x;
            ksT[(d0 + 1) * KST_STRIDE + s] = v.y;
            ksT[(d0 + 2) * KST_STRIDE + s] = v.z;
            ksT[(d0 + 3) * KST_STRIDE + s] = v.w;
        }
    }
    __syncthreads();

    int t = tt * 8 + w;
    int bt = b * NT + t;
    const float* qrow = g_qk + (size_t)bt * D;

    float acc = 0.f;
#pragma unroll 4
    for (int d0 = 0; d0 < D; d0 += 4) {
        float4 q4 = *(const float4*)(qrow + d0);
        float k0 = ksT[(d0 + 0) * KST_STRIDE + lane];
        float k1 = ksT[(d0 + 1) * KST_STRIDE + lane];
        float k2 = ksT[(d0 + 2) * KST_STRIDE + lane];
        float k3 = ksT[(d0 + 3) * KST_STRIDE + lane];
        acc += q4.x * k0 + q4.y * k1 + q4.z * k2 + q4.w * k3;
    }
    float sc = acc * 0.03125f;
    float m = warp_max_all(sc);
    float e = expf(sc - m);
    float sum = warp_sum_all(e);
    float a = e / sum;
    g_attn[(size_t)bt * NS + lane] = a;

    float mw = g_xw[512 + b * NS + lane];
    float dot = warp_sum_all(a * mw);
    if (lane == 0) {
        float v = g_xw[bt] + dot + bpv[0];
        float zz = (v - 0.5f) * 10.f;
        out[bt] = 1.f / (1.f + expf(-zz));
    }
}

// ---------------------------------------------------------------------------
// fused_out: block bt zeros its 50257-float row, then atomicAdds its 512
// contributions (L2-hit, just-written lines).
// ---------------------------------------------------------------------------
__global__ __launch_bounds__(256) void fused_out(
    const int* __restrict__ ids, float* __restrict__ out)
{
    int bt = blockIdx.x;
    int b = bt >> 6;
    int tid = threadIdx.x;

    __shared__ float att[NS];
    __shared__ float sal_s[NS * NE];
    __shared__ int ids_s[NS * NE];

    if (tid < NS) att[tid] = g_attn[(size_t)bt * NS + tid];
    for (int i = tid; i < NS * NE; i += 256) {
        sal_s[i] = g_sal[(size_t)b * NS * NE + i];
        ids_s[i] = ids[(size_t)b * NS * NE + i];
    }

    float* base = out + 512 + (size_t)bt * NV;
    int pad = (4 - (bt & 3)) & 3;          // (512 + bt*NV) mod 4 == bt mod 4
    for (int i = tid; i < pad; i += 256) base[i] = 0.f;
    int n4 = (NV - pad) >> 2;
    float4* b4 = (float4*)(base + pad);
    float4 z4 = make_float4(0.f, 0.f, 0.f, 0.f);
    for (int i = tid; i < n4; i += 256) b4[i] = z4;
    int done = pad + n4 * 4;
    for (int i = done + tid; i < NV; i += 256) base[i] = 0.f;
    __syncthreads();

    for (int i = tid; i < NS * NE; i += 256) {
        int s = i >> 4;
        float val = att[s] * sal_s[i];
        if (val != 0.f) atomicAdd(base + ids_s[i], val);
    }
}

// ---------------------------------------------------------------------------
extern "C" void kernel_launch(void* const* d_in, const int* in_sizes, int n_in,
                              void* d_out, int out_size)
{
    const float* x   = (const float*)d_in[0];
    const float* mem = (const float*)d_in[1];
    const float* emb = (const float*)d_in[2];
    const int*   ids = (const int*)d_in[3];
    const float* Wq  = (const float*)d_in[4];
    const float* bq  = (const float*)d_in[5];
    const float* Wk  = (const float*)d_in[6];
    const float* bk  = (const float*)d_in[7];
    const float* Wp  = (const float*)d_in[8];
    const float* bp  = (const float*)d_in[9];
    float* out = (float*)d_out;

    cudaFuncSetAttribute(mma_gemm, cudaFuncAttributeMaxDynamicSharedMemorySize, SM_TOTAL);
    cudaFuncSetAttribute(attn2, cudaFuncAttributeMaxDynamicSharedMemorySize, ATTN_SMEM);

    prep_everything<<<3168, 256>>>(x, mem, emb, ids, Wq, Wk, Wp);
    mma_gemm<<<dim3(8, 6), 256, SM_TOTAL>>>(x, mem, Wq, Wk, bq, bk);
    attn2<<<dim3(8, 8), 256, ATTN_SMEM>>>(bp, out);
    fused_out<<<NB * NT, 256>>>(ids, out);
}

// round 6
// speedup vs baseline: 1.4647x; 1.2088x over previous
#include <cuda_runtime.h>
#include <cuda_bf16.h>
#include <cstdint>

#define D 1024
#define NB 8
#define NT 64
#define NS 32
#define NE 16
#define NV 50257
#define M_TOT 768          // 512 q rows + 256 k rows
#define OUT_F4 6433024     // (512 + 8*64*50257) / 4

// tcgen05 only exists in the arch-SPECIFIC (sm_103a) device pass.
#if defined(__CUDA_ARCH_FEAT_SM103_ALL) || \
    (defined(__CUDA_ARCH_SPECIFIC__) && (__CUDA_ARCH_SPECIFIC__ == 1030))
#define HAS_TCGEN05 1
#else
#define HAS_TCGEN05 0
#endif

// ---------------- scratch (device globals; no allocation allowed) ----------
__device__ __nv_bfloat16 g_ahi[M_TOT * D];
__device__ __nv_bfloat16 g_alo[M_TOT * D];
__device__ __nv_bfloat16 g_whi[2 * D * D];   // transposed: [z][n][k]
__device__ __nv_bfloat16 g_wlo[2 * D * D];
__device__ float g_qk[M_TOT * D];            // rows 0-511: q, 512-767: k
__device__ float g_sal[NB * NS * NE];
__device__ float g_xw[M_TOT];                // [0,512): x.Wp1  [512,768): mem.Wp2

// ---------------- PTX helpers ---------------------------------------------
__device__ __forceinline__ uint32_t smem_u32(const void* p) {
    uint32_t a;
    asm("{ .reg .u64 t; cvta.to.shared.u64 t, %1; cvt.u32.u64 %0, t; }"
        : "=r"(a) : "l"(p));
    return a;
}
__device__ __forceinline__ uint32_t elect1() {
    uint32_t p;
    asm volatile("{\n\t.reg .pred p;\n\telect.sync _|p, 0xFFFFFFFF;\n\t"
                 "selp.b32 %0, 1, 0, p;\n\t}" : "=r"(p));
    return p;
}
#define MBARRIER_INIT(a, c) \
    asm volatile("mbarrier.init.shared.b64 [%0], %1;" :: "r"(a), "r"(c) : "memory")
#define MBARRIER_INVAL(a) \
    asm volatile("mbarrier.inval.shared.b64 [%0];" :: "r"(a) : "memory")
#define MBARRIER_WAIT_PARITY(mb, ph) do {                                        \
    uint32_t _m = (mb), _p = (ph), _d;                                           \
    asm volatile("{\n\t.reg .pred p;\n\t"                                        \
        "mbarrier.try_wait.parity.acquire.cta.shared::cta.b64 p, [%1], %2;\n\t"  \
        "selp.b32 %0, 1, 0, p;\n\t}" : "=r"(_d) : "r"(_m), "r"(_p) : "memory");  \
    if (!_d) {                                                                   \
        asm volatile("{\n\t.reg .pred P1;\n\t"                                   \
          "WL_%=:\n\t"                                                           \
          "mbarrier.try_wait.parity.acquire.cta.shared::cta.b64 P1, [%0], %1, 0x989680;\n\t" \
          "@P1 bra.uni WD_%=;\n\t"                                               \
          "bra.uni WL_%=;\n\t"                                                   \
          "WD_%=:\n\t}" :: "r"(_m), "r"(_p) : "memory");                         \
    }                                                                            \
} while (0)

#define CP_ASYNC16(dst, src) \
    asm volatile("cp.async.cg.shared.global [%0], [%1], 16;" \
                 :: "r"(dst), "l"(src) : "memory")
#define CP_COMMIT() asm volatile("cp.async.commit_group;" ::: "memory")
#define CP_WAIT2()  asm volatile("cp.async.wait_group 2;" ::: "memory")
#define CP_WAIT0()  asm volatile("cp.async.wait_group 0;" ::: "memory")

#if HAS_TCGEN05
#define TCGEN05_ALLOC(sa, n) \
    asm volatile("tcgen05.alloc.cta_group::1.sync.aligned.shared::cta.b32 [%0], %1;" \
                 :: "r"((uint32_t)(sa)), "r"((uint32_t)(n)) : "memory")
#define TCGEN05_DEALLOC(t, n) \
    asm volatile("tcgen05.dealloc.cta_group::1.sync.aligned.b32 %0, %1;" :: "r"(t), "r"(n))
#define TCGEN05_RELINQ() \
    asm volatile("tcgen05.relinquish_alloc_permit.cta_group::1.sync.aligned;")
#define TCGEN05_COMMIT(mb) \
    asm volatile("tcgen05.commit.cta_group::1.mbarrier::arrive::one.shared::cluster.b64 [%0];" \
                 :: "r"((uint32_t)(mb)) : "memory")
#define TCGEN05_FENCE_AFTER() \
    asm volatile("tcgen05.fence::after_thread_sync;" ::: "memory")
#define TCGEN05_FENCE_BEFORE() \
    asm volatile("tcgen05.fence::before_thread_sync;" ::: "memory")
#define TCGEN05_WAIT_LD() asm volatile("tcgen05.wait::ld.sync.aligned;" ::: "memory")
#define FENCE_PROXY_ASYNC() \
    asm volatile("fence.proxy.async.shared::cta;" ::: "memory")
#define TCGEN05_LD_32X32B_X32(r, ta) \
    asm volatile( \
        "tcgen05.ld.sync.aligned.32x32b.x32.b32 " \
        "{%0, %1, %2, %3, %4, %5, %6, %7, " \
        " %8, %9, %10, %11, %12, %13, %14, %15, " \
        " %16, %17, %18, %19, %20, %21, %22, %23, " \
        " %24, %25, %26, %27, %28, %29, %30, %31}, [%32];" \
        : "=r"((r)[0]),  "=r"((r)[1]),  "=r"((r)[2]),  "=r"((r)[3]), \
          "=r"((r)[4]),  "=r"((r)[5]),  "=r"((r)[6]),  "=r"((r)[7]), \
          "=r"((r)[8]),  "=r"((r)[9]),  "=r"((r)[10]), "=r"((r)[11]), \
          "=r"((r)[12]), "=r"((r)[13]), "=r"((r)[14]), "=r"((r)[15]), \
          "=r"((r)[16]), "=r"((r)[17]), "=r"((r)[18]), "=r"((r)[19]), \
          "=r"((r)[20]), "=r"((r)[21]), "=r"((r)[22]), "=r"((r)[23]), \
          "=r"((r)[24]), "=r"((r)[25]), "=r"((r)[26]), "=r"((r)[27]), \
          "=r"((r)[28]), "=r"((r)[29]), "=r"((r)[30]), "=r"((r)[31]) \
        : "r"(ta))

__device__ __forceinline__ void mma_f16_ss(uint32_t d, uint64_t a, uint64_t b,
                                           uint32_t idesc, uint32_t en) {
    asm volatile("{\n\t.reg .pred p;\n\tsetp.ne.u32 p, %5, 0;\n\t"
        "tcgen05.mma.cta_group::1.kind::f16 [%0], %1, %2, %3, {%4,%4,%4,%4}, p;\n\t}"
        :: "r"(d), "l"(a), "l"(b), "r"(idesc), "r"(0u), "r"(en) : "memory");
}
#endif  // HAS_TCGEN05

#define SWZ(b) ((b) ^ (((b) >> 3) & 0x70))
static constexpr uint64_t DESC_BASE_SW128 =
    (uint64_t(2) << 61) | (uint64_t(1) << 46) | (uint64_t(64) << 32) | (uint64_t(1) << 16);
#define MAKE_DESC(a) (DESC_BASE_SW128 | ((uint64_t)((a) >> 4) & 0x3FFF))

// idesc: kind::f16, dtype=F32, atype=BF16, btype=BF16, N=128, M=128
static constexpr uint32_t GEMM_IDESC =
    (1u << 4) | (1u << 7) | (1u << 10) | ((128u / 8u) << 17) | ((128u / 16u) << 24);

__device__ __forceinline__ float warp_sum(float v) {
#pragma unroll
    for (int o = 16; o > 0; o >>= 1) v += __shfl_down_sync(0xffffffffu, v, o);
    return v;
}
__device__ __forceinline__ float warp_sum_all(float v) {
#pragma unroll
    for (int o = 16; o > 0; o >>= 1) v += __shfl_xor_sync(0xffffffffu, v, o);
    return v;
}
__device__ __forceinline__ float warp_max_all(float v) {
#pragma unroll
    for (int o = 16; o > 0; o >>= 1) v = fmaxf(v, __shfl_xor_sync(0xffffffffu, v, o));
    return v;
}

// ---------------------------------------------------------------------------
// prep_everything: one kernel, 3168 blocks x 256 threads.
//  [0,768)      : fp32 -> bf16 hi/lo split of [x ; mem]
//  [768,864)    : p_gen partial dots xw
//  [864,1120)   : salience softmax (per b,s)
//  [1120,3168)  : W transpose + hi/lo split
// ---------------------------------------------------------------------------
__global__ __launch_bounds__(256) void prep_everything(
    const float* __restrict__ x, const float* __restrict__ mem,
    const float* __restrict__ emb, const int* __restrict__ ids,
    const float* __restrict__ Wq, const float* __restrict__ Wk,
    const float* __restrict__ Wp)
{
    __shared__ float shbuf[1100];      // union: sal dl[1024]+sc[16] / cvt_w t[32][33]
    __shared__ int id_s[NE];
    int bid = blockIdx.x;
    int tid = threadIdx.x;

    if (bid < 768) {
        // ---- cvt_inputs ----
        int i = bid * 256 + tid;
        const float4* src = (i < 131072) ? ((const float4*)x + i)
                                         : ((const float4*)mem + (i - 131072));
        float4 v = *src;
        int base = i * 4;
        float f[4] = {v.x, v.y, v.z, v.w};
#pragma unroll
        for (int j = 0; j < 4; j++) {
            __nv_bfloat16 h = __float2bfloat16(f[j]);
            g_ahi[base + j] = h;
            g_alo[base + j] = __float2bfloat16(f[j] - __bfloat162float(h));
        }
    } else if (bid < 864) {
        // ---- prep_pgen ----
        int row = (bid - 768) * 8 + (tid >> 5);
        int lane = tid & 31;
        const float* src = (row < 512) ? (x + (size_t)row * D)
                                       : (mem + (size_t)(row - 512) * D);
        const float* w = (row < 512) ? Wp : (Wp + D);
        float p = 0.f;
        for (int d = lane; d < D; d += 32) p += src[d] * w[d];
        p = warp_sum(p);
        if (lane == 0) g_xw[row] = p;
    } else if (bid < 1120) {
        // ---- salience ----
        int bs = bid - 864;
        int b = bs >> 5;
        int lane = tid & 31, w = tid >> 5;
        float* dl = shbuf;
        float* sc = shbuf + 1024;

        const float* xl = x + (size_t)(b * NT + NT - 1) * D;
        for (int i = tid; i < D; i += 256) dl[i] = xl[i];
        if (tid < NE) id_s[tid] = ids[(size_t)bs * NE + tid];
        __syncthreads();

#pragma unroll
        for (int j = 0; j < 2; j++) {
            int e = w * 2 + j;
            const float* er = emb + (size_t)id_s[e] * D;
            float p = 0.f;
            for (int d = lane; d < D; d += 32) p += dl[d] * er[d];
            p = warp_sum(p);
            if (lane == 0) sc[e] = p;
        }
        __syncthreads();

        if (tid == 0) {
            float m = sc[0];
            for (int e = 1; e < NE; e++) m = fmaxf(m, sc[e]);
            float a[NE];
            float sum = 0.f;
            for (int e = 0; e < NE; e++) { a[e] = expf(sc[e] - m); sum += a[e]; }
            float inv = 1.f / sum;
            for (int e = 0; e < NE; e++) {
                float val = a[e] * inv;
                for (int e2 = e + 1; e2 < NE; e2++)
                    if (id_s[e2] == id_s[e]) { val = 0.f; break; }
                g_sal[(size_t)bs * NE + e] = val;
            }
        }
    } else {
        // ---- cvt_w (transpose + split) ----
        int zz = bid - 1120;                  // 0..2047
        int z = zz >> 10;
        int rem = zz & 1023;
        int k0 = (rem >> 5) * 32, n0 = (rem & 31) * 32;
        const float* W = z ? Wk : Wq;
        size_t zoff = (size_t)z * D * D;
        float (*t)[33] = (float(*)[33])shbuf;
        int tx = tid & 31, ty = tid >> 5;
#pragma unroll
        for (int j = 0; j < 4; j++)
            t[ty + j * 8][tx] = W[(size_t)(k0 + ty + j * 8) * D + n0 + tx];
        __syncthreads();
#pragma unroll
        for (int j = 0; j < 4; j++) {
            float v = t[tx][ty + j * 8];
            size_t o = zoff + (size_t)(n0 + ty + j * 8) * D + k0 + tx;
            __nv_bfloat16 h = __float2bfloat16(v);
            g_whi[o] = h;
            g_wlo[o] = __float2bfloat16(v - __bfloat162float(h));
        }
    }
}

// ---------------------------------------------------------------------------
// mma_gemm + output zeroing in ONE launch. 1D grid of 2048 blocks:
//   blocks [0,48):   tcgen05 GEMM tiles (tm = bid/8, tn = bid%8)
//   blocks [48,2048): zero 103MB output (overlaps with GEMM on other SMs;
//                     output fits in 126MB L2 -> later atomics are L2 hits)
// 3-stage cp.async pipeline; per-stage mbarriers gate stage reuse.
// ---------------------------------------------------------------------------
#define SM_MBAR0  0
#define SM_MBAR1  8
#define SM_MBAR2  16
#define SM_TPTR   32
#define SM_STAGE  65536
#define SM_BASE   1024
#define SM_TOTAL  (SM_BASE + 3 * SM_STAGE)   // 197632
#define NZERO_BLK 2000

#if HAS_TCGEN05
__device__ __forceinline__ void load_tile_async(uint32_t soff,
                                                const __nv_bfloat16* __restrict__ src)
{
    int tid = threadIdx.x;
#pragma unroll
    for (int i = 0; i < 4; i++) {
        int idx = tid + i * 256;                    // 0..1023
        int row = idx >> 3, c8 = idx & 7;
        uint32_t b = row * 128 + c8 * 16;
        CP_ASYNC16(soff + SWZ(b), (const char*)(src + (size_t)row * D + c8 * 8));
    }
}
#endif

__global__ __launch_bounds__(256, 1) void mma_gemm(
    const float* __restrict__ x, const float* __restrict__ mem,
    const float* __restrict__ Wq, const float* __restrict__ Wk,
    const float* __restrict__ bq, const float* __restrict__ bk,
    float* __restrict__ out)
{
    extern __shared__ char smem[];
    int tid = threadIdx.x;
    int bid = blockIdx.x;

    if (bid >= 48) {
        // ----- zero blocks -----
        float4 z4 = make_float4(0.f, 0.f, 0.f, 0.f);
        float4* o4 = (float4*)out;
        for (size_t i = (size_t)(bid - 48) * 256 + tid; i < OUT_F4;
             i += (size_t)NZERO_BLK * 256)
            o4[i] = z4;
        return;
    }

    int tm = bid >> 3, tn = bid & 7;
    int m0 = tm * 128, n0 = tn * 128;

#if HAS_TCGEN05
    (void)x; (void)mem; (void)Wq; (void)Wk;
    uint32_t sb = smem_u32(smem);
    int wid = tid >> 5, lane = tid & 31;
    int z = (tm >= 4);

    const __nv_bfloat16* ahi = g_ahi + (size_t)m0 * D;
    const __nv_bfloat16* alo = g_alo + (size_t)m0 * D;
    const __nv_bfloat16* bhi = g_whi + (size_t)z * D * D + (size_t)n0 * D;
    const __nv_bfloat16* blo = g_wlo + (size_t)z * D * D + (size_t)n0 * D;

    if (wid == 0) TCGEN05_ALLOC(sb + SM_TPTR, 128);
    if (tid == 0) {
        MBARRIER_INIT(sb + SM_MBAR0, 1);
        MBARRIER_INIT(sb + SM_MBAR1, 1);
        MBARRIER_INIT(sb + SM_MBAR2, 1);
    }
    __syncthreads();
    uint32_t tmem;
    asm volatile("ld.shared.b32 %0, [%1];" : "=r"(tmem) : "r"(sb + SM_TPTR));

    // prologue: chunks 0,1,2
#pragma unroll
    for (int c = 0; c < 3; c++) {
        uint32_t so = sb + SM_BASE + c * SM_STAGE;
        load_tile_async(so,         ahi + c * 64);
        load_tile_async(so + 16384, alo + c * 64);
        load_tile_async(so + 32768, bhi + c * 64);
        load_tile_async(so + 49152, blo + c * 64);
        CP_COMMIT();
    }

    for (int c = 0; c < 16; c++) {
        int stg = c - (c / 3) * 3;
        uint32_t so = sb + SM_BASE + stg * SM_STAGE;
        uint32_t mb = sb + stg * 8;                 // SM_MBAR{0,1,2}
        CP_WAIT2();
        __syncthreads();                            // chunk c visible to CTA
        if (wid == 0 && elect1()) {
            FENCE_PROXY_ASYNC();
            uint64_t dah = MAKE_DESC(so);
            uint64_t dal = MAKE_DESC(so + 16384);
            uint64_t dbh = MAKE_DESC(so + 32768);
            uint64_t dbl = MAKE_DESC(so + 49152);
#pragma unroll
            for (int s = 0; s < 4; s++) {
                uint64_t o = s * 2;
                mma_f16_ss(tmem, dah + o, dbh + o, GEMM_IDESC, !(c == 0 && s == 0));
                mma_f16_ss(tmem, dah + o, dbl + o, GEMM_IDESC, 1u);
                mma_f16_ss(tmem, dal + o, dbh + o, GEMM_IDESC, 1u);
            }
            TCGEN05_COMMIT(mb);
        }
        if (c <= 12) {
            // refill stage stg with chunk c+3 once MMA(c) (commit #(c/3+1)) done
            MBARRIER_WAIT_PARITY(mb, (c / 3) & 1);
            int cn = c + 3;
            load_tile_async(so,         ahi + cn * 64);
            load_tile_async(so + 16384, alo + cn * 64);
            load_tile_async(so + 32768, bhi + cn * 64);
            load_tile_async(so + 49152, blo + cn * 64);
            CP_COMMIT();
        }
    }
    CP_WAIT0();
    // stage0: 6 commits -> parity 1; stages 1,2: 5 commits -> parity 0
    MBARRIER_WAIT_PARITY(sb + SM_MBAR0, 1);
    MBARRIER_WAIT_PARITY(sb + SM_MBAR1, 0);
    MBARRIER_WAIT_PARITY(sb + SM_MBAR2, 0);
    TCGEN05_FENCE_AFTER();

    if (wid < 4) {
        uint32_t dr[128];
#pragma unroll
        for (int b = 0; b < 128; b += 32) TCGEN05_LD_32X32B_X32(dr + b, tmem + b);
        TCGEN05_WAIT_LD();
        TCGEN05_FENCE_BEFORE();
        int m = m0 + wid * 32 + lane;
        const float* bias = (m < 512) ? bq : bk;
        float* crow = g_qk + (size_t)m * D + n0;
#pragma unroll 8
        for (int cc = 0; cc < 128; cc++)
            crow[cc] = __uint_as_float(dr[cc]) + __ldg(&bias[n0 + cc]);
    }
    __syncthreads();
    if (tid == 0) {
        MBARRIER_INVAL(sb + SM_MBAR0);
        MBARRIER_INVAL(sb + SM_MBAR1);
        MBARRIER_INVAL(sb + SM_MBAR2);
    }
    __syncthreads();
    if (wid == 0) {
        TCGEN05_RELINQ();
        TCGEN05_DEALLOC(tmem, 128);
    }
#else
    // ---------------- SIMT fp32 fallback: 128x128 tile, BK=16, 8x8 micro ---
    float* As = (float*)smem;                    // [16][132] transposed A
    float* Bs = (float*)(smem + 16 * 132 * 4);   // [16][128]
    const float* Asrc = (m0 < 512) ? (x + (size_t)m0 * D)
                                   : (mem + (size_t)(m0 - 512) * D);
    const float* W = (m0 < 512) ? Wq : Wk;
    const float* bias = (m0 < 512) ? bq : bk;
    int tr = tid >> 4, tc = tid & 15;

    float acc[8][8];
#pragma unroll
    for (int i = 0; i < 8; i++)
#pragma unroll
        for (int j = 0; j < 8; j++) acc[i][j] = 0.f;

    for (int k0 = 0; k0 < D; k0 += 16) {
#pragma unroll
        for (int i = 0; i < 2; i++) {
            int f4 = tid * 2 + i;
            int row = f4 >> 2;
            int c4 = (f4 & 3) * 4;
            float4 v = *(const float4*)(Asrc + (size_t)row * D + k0 + c4);
            As[(c4 + 0) * 132 + row] = v.x;
            As[(c4 + 1) * 132 + row] = v.y;
            As[(c4 + 2) * 132 + row] = v.z;
            As[(c4 + 3) * 132 + row] = v.w;
        }
#pragma unroll
        for (int i = 0; i < 2; i++) {
            int f4 = tid * 2 + i;
            int row = f4 >> 5;
            int cc = (f4 & 31) * 4;
            *(float4*)(Bs + row * 128 + cc) =
                *(const float4*)(W + (size_t)(k0 + row) * D + n0 + cc);
        }
        __syncthreads();
#pragma unroll
        for (int kk = 0; kk < 16; kk++) {
            float a[8], bb[8];
#pragma unroll
            for (int i = 0; i < 8; i++) a[i] = As[kk * 132 + tr * 8 + i];
#pragma unroll
            for (int j = 0; j < 8; j++) bb[j] = Bs[kk * 128 + tc * 8 + j];
#pragma unroll
            for (int i = 0; i < 8; i++)
#pragma unroll
                for (int j = 0; j < 8; j++) acc[i][j] += a[i] * bb[j];
        }
        __syncthreads();
    }
#pragma unroll
    for (int i = 0; i < 8; i++) {
        int m = m0 + tr * 8 + i;
        float* crow = g_qk + (size_t)m * D + n0 + tc * 8;
#pragma unroll
        for (int j = 0; j < 8; j++) crow[j] = acc[i][j] + bias[n0 + tc * 8 + j];
    }
#endif
}

// ---------------------------------------------------------------------------
// attn_scatter: grid (8 t-tiles, 8 b), 256 threads.
// k[b] transposed in smem; warp w handles row t = tt*8+w, lane = s.
// scores -> softmax -> p_gen AND the pointer-prob atomics (attn never stored).
// smem: ksT [D][33] + sal_s[512] + ids_s[512]
// ---------------------------------------------------------------------------
#define KST_STRIDE 33
#define AS_KST   (D * KST_STRIDE)               // floats
#define AS_SAL   (AS_KST)                       // offset in floats
#define AS_IDS   (AS_KST + NS * NE)
#define ATTN_SMEM ((AS_IDS + NS * NE) * 4)      // bytes = 139264

__global__ __launch_bounds__(256, 1) void attn_scatter(
    const float* __restrict__ bpv, const int* __restrict__ ids,
    float* __restrict__ out)
{
    extern __shared__ float ksT[];
    float* sal_s = ksT + AS_SAL;
    int*   ids_s = (int*)(ksT + AS_IDS);

    int tt = blockIdx.x, b = blockIdx.y;
    int tid = threadIdx.x;
    int w = tid >> 5, lane = tid & 31;

    {
        int s = tid >> 3, dg = tid & 7;
        const float* krow = g_qk + (size_t)(512 + b * NS + s) * D;
#pragma unroll
        for (int j = 0; j < 32; j++) {
            int d0 = (dg + j * 8) * 4;
            float4 v = *(const float4*)(krow + d0);
            ksT[(d0 + 0) * KST_STRIDE + s] = v.x;
            ksT[(d0 + 1) * KST_STRIDE + s] = v.y;
            ksT[(d0 + 2) * KST_STRIDE + s] = v.z;
            ksT[(d0 + 3) * KST_STRIDE + s] = v.w;
        }
    }
    for (int i = tid; i < NS * NE; i += 256) {
        sal_s[i] = g_sal[(size_t)b * NS * NE + i];
        ids_s[i] = ids[(size_t)b * NS * NE + i];
    }
    __syncthreads();

    int t = tt * 8 + w;
    int bt = b * NT + t;
    const float* qrow = g_qk + (size_t)bt * D;

    float acc = 0.f;
#pragma unroll 4
    for (int d0 = 0; d0 < D; d0 += 4) {
        float4 q4 = *(const float4*)(qrow + d0);
        float k0 = ksT[(d0 + 0) * KST_STRIDE + lane];
        float k1 = ksT[(d0 + 1) * KST_STRIDE + lane];
        float k2 = ksT[(d0 + 2) * KST_STRIDE + lane];
        float k3 = ksT[(d0 + 3) * KST_STRIDE + lane];
        acc += q4.x * k0 + q4.y * k1 + q4.z * k2 + q4.w * k3;
    }
    float sc = acc * 0.03125f;
    float m = warp_max_all(sc);
    float e = expf(sc - m);
    float sum = warp_sum_all(e);
    float a = e / sum;                     // attn[b][t][s=lane]

    // p_gen
    float mw = g_xw[512 + b * NS + lane];
    float dot = warp_sum_all(a * mw);
    if (lane == 0) {
        float v = g_xw[bt] + dot + bpv[0];
        float zz = (v - 0.5f) * 10.f;
        out[bt] = 1.f / (1.f + expf(-zz));
    }

    // pointer-prob scatter: lane s handles its 16 entity slots
    float* base = out + 512 + (size_t)bt * NV;
#pragma unroll
    for (int ei = 0; ei < NE; ei++) {
        float val = a * sal_s[lane * NE + ei];
        if (val != 0.f) atomicAdd(base + ids_s[lane * NE + ei], val);
    }
}

// ---------------------------------------------------------------------------
extern "C" void kernel_launch(void* const* d_in, const int* in_sizes, int n_in,
                              void* d_out, int out_size)
{
    const float* x   = (const float*)d_in[0];
    const float* mem = (const float*)d_in[1];
    const float* emb = (const float*)d_in[2];
    const int*   ids = (const int*)d_in[3];
    const float* Wq  = (const float*)d_in[4];
    const float* bq  = (const float*)d_in[5];
    const float* Wk  = (const float*)d_in[6];
    const float* bk  = (const float*)d_in[7];
    const float* Wp  = (const float*)d_in[8];
    const float* bp  = (const float*)d_in[9];
    float* out = (float*)d_out;

    cudaFuncSetAttribute(mma_gemm, cudaFuncAttributeMaxDynamicSharedMemorySize, SM_TOTAL);
    cudaFuncSetAttribute(attn_scatter, cudaFuncAttributeMaxDynamicSharedMemorySize, ATTN_SMEM);

    prep_everything<<<3168, 256>>>(x, mem, emb, ids, Wq, Wk, Wp);
    mma_gemm<<<48 + NZERO_BLK, 256, SM_TOTAL>>>(x, mem, Wq, Wk, bq, bk, out);
    attn_scatter<<<dim3(8, 8), 256, ATTN_SMEM>>>(bp, ids, out);
}